// round 1
// baseline (speedup 1.0000x reference)
#include <cuda_runtime.h>

#define G        64
#define IMGSZ    512
#define NTHREADS 256

// Bounds-checked image load (zero padding outside the 512x512 image).
__device__ __forceinline__ float ldimg(const float* __restrict__ img, int gy, int gx) {
    if ((unsigned)gy < IMGSZ && (unsigned)gx < IMGSZ)
        return __ldg(img + gy * IMGSZ + gx);
    return 0.0f;
}

// Separable antialiased triangle downsample by integer factor S of a
// PS x PS (PS = 64*S) crop whose top-left image coordinate is (by, bx).
// Horizontal pass -> smem tmp[PS][64], vertical pass -> o[64][64].
// Edge renormalization matches jax.image.resize: taps outside the PATCH
// are dropped and remaining weights renormalized; taps inside the patch
// but outside the image contribute value 0 with full weight.
template <int S>
__device__ void downsample(const float* __restrict__ img, float* __restrict__ o,
                           int by, int bx, float* __restrict__ tmp) {
    constexpr int PS = G * S;
    constexpr int NT = 2 * S;   // tap count
    const int tid = threadIdx.x;

    // ---- Phase 1: horizontal (PS rows x 64 output cols) ----
    for (int idx = tid; idx < PS * G; idx += NTHREADS) {
        int r  = idx >> 6;
        int i  = idx & (G - 1);
        int gy = by + r;
        int j0 = S * i - S / 2;
        float acc = 0.0f, wsum = 0.0f;
#pragma unroll
        for (int k = 0; k < NT; k++) {
            int j = j0 + k;
            if (j >= 0 && j < PS) {
                float w = (1.0f - fabsf((float)k - ((float)S - 0.5f)) / (float)S) / (float)S;
                acc  += w * ldimg(img, gy, bx + j);
                wsum += w;
            }
        }
        tmp[idx] = acc / wsum;   // wsum == 1.0f exactly in the interior
    }
    __syncthreads();

    // ---- Phase 2: vertical (64 x 64 output) ----
    for (int idx = tid; idx < G * G; idx += NTHREADS) {
        int y  = idx >> 6;
        int x  = idx & (G - 1);
        int r0 = S * y - S / 2;
        float acc = 0.0f, wsum = 0.0f;
#pragma unroll
        for (int k = 0; k < NT; k++) {
            int r = r0 + k;
            if (r >= 0 && r < PS) {
                float w = (1.0f - fabsf((float)k - ((float)S - 0.5f)) / (float)S) / (float)S;
                acc  += w * tmp[r * G + x];
                wsum += w;
            }
        }
        o[idx] = acc / wsum;
    }
}

// Grid: 576 blocks. [0,192): scale-4 (heavy, scheduled first),
// [192,384): scale-2, [384,576): direct 64x64 copy. bc -> (b, c).
__global__ void glimpse_kernel(const float* __restrict__ img0,
                               const float* __restrict__ img2,
                               const float* __restrict__ img4,
                               const float* __restrict__ loc,
                               float* __restrict__ out) {
    extern __shared__ float tmp[];

    int blk = blockIdx.x;
    int sel = blk / 192;              // 0: S=4, 1: S=2, 2: copy
    int bc  = blk - sel * 192;
    int b   = bc / 3;
    int c   = bc - b * 3;

    // start index, matching jnp: trunc(0.5f * ((loc + 1.0f) * 511.0f))
    float lx = loc[2 * b + 0];
    float ly = loc[2 * b + 1];
    int sx = (int)(0.5f * ((lx + 1.0f) * 511.0f));
    int sy = (int)(0.5f * ((ly + 1.0f) * 511.0f));

    if (sel == 2) {
        // window 0: plain 64x64 zero-padded crop of img0
        const float* img = img0 + (size_t)(b * 3 + c) * IMGSZ * IMGSZ;
        float* o = out + (size_t)((b * 3 + 0) * 3 + c) * G * G;
        int by = sy - G / 2, bx = sx - G / 2;
        for (int idx = threadIdx.x; idx < G * G; idx += NTHREADS) {
            int y = idx >> 6, x = idx & (G - 1);
            o[idx] = ldimg(img, by + y, bx + x);
        }
    } else if (sel == 1) {
        // window 1: 128x128 crop of img2, downsample x2
        const float* img = img2 + (size_t)(b * 3 + c) * IMGSZ * IMGSZ;
        float* o = out + (size_t)((b * 3 + 1) * 3 + c) * G * G;
        downsample<2>(img, o, sy - 64, sx - 64, tmp);
    } else {
        // window 2: 256x256 crop of img4, downsample x4
        const float* img = img4 + (size_t)(b * 3 + c) * IMGSZ * IMGSZ;
        float* o = out + (size_t)((b * 3 + 2) * 3 + c) * G * G;
        downsample<4>(img, o, sy - 128, sx - 128, tmp);
    }
}

extern "C" void kernel_launch(void* const* d_in, const int* in_sizes, int n_in,
                              void* d_out, int out_size) {
    const float* img0 = (const float*)d_in[0];
    const float* img2 = (const float*)d_in[1];
    const float* img4 = (const float*)d_in[2];
    const float* loc  = (const float*)d_in[3];
    float* out = (float*)d_out;

    const size_t smem = (size_t)(G * 4) * G * sizeof(float);  // 256*64*4 = 64 KB
    cudaFuncSetAttribute(glimpse_kernel,
                         cudaFuncAttributeMaxDynamicSharedMemorySize, (int)smem);
    glimpse_kernel<<<576, NTHREADS, smem>>>(img0, img2, img4, loc, out);
}

// round 2
// speedup vs baseline: 1.9933x; 1.9933x over previous
#include <cuda_runtime.h>

#define G        64
#define IMGSZ    512
#define NTHREADS 256

// Bounds-checked image load (zero padding outside the 512x512 image).
__device__ __forceinline__ float ldimg(const float* __restrict__ img, int gy, int gx) {
    if ((unsigned)gy < IMGSZ && (unsigned)gx < IMGSZ)
        return __ldg(img + gy * IMGSZ + gx);
    return 0.0f;
}

// Separable antialiased triangle downsample by integer factor S, computing a
// slice of ROWS output rows starting at y0. Input crop top-left = (by, bx).
// Horizontal pass -> smem tmp[S*ROWS + S][64], vertical pass -> o rows.
// Renormalization semantics match jax.image.resize: taps outside the PATCH
// ([0, 64*S)) are dropped with weight renormalization; taps inside the patch
// but outside the image contribute 0 with full weight (zero-pad crop).
template <int S, int ROWS>
__device__ void downsample_slice(const float* __restrict__ img, float* __restrict__ o,
                                 int by, int bx, int y0, float* __restrict__ tmp) {
    constexpr int PS = G * S;          // patch size
    constexpr int NT = 2 * S;          // tap count
    constexpr int LR = S * ROWS + S;   // local input rows in this slice
    const int tid = threadIdx.x;
    const int rb = S * y0 - S / 2;     // absolute patch row of tmp[0]

    // ---- Phase 1: horizontal filter (LR rows x 64 output cols) ----
    for (int idx = tid; idx < LR * G; idx += NTHREADS) {
        int lr = idx >> 6;
        int r  = rb + lr;
        if ((unsigned)r >= (unsigned)PS) continue;  // outside patch: never read
        int i  = idx & (G - 1);
        int gy = by + r;
        int j0 = S * i - S / 2;
        float acc = 0.0f, wsum = 0.0f;
#pragma unroll
        for (int k = 0; k < NT; k++) {
            int j = j0 + k;
            if (j >= 0 && j < PS) {
                float w = (1.0f - fabsf((float)k - ((float)S - 0.5f)) / (float)S) / (float)S;
                acc  += w * ldimg(img, gy, bx + j);
                wsum += w;
            }
        }
        tmp[idx] = acc / wsum;   // wsum == 1.0f exactly in the interior
    }
    __syncthreads();

    // ---- Phase 2: vertical filter (ROWS x 64 output) ----
    for (int idx = tid; idx < ROWS * G; idx += NTHREADS) {
        int y  = y0 + (idx >> 6);
        int x  = idx & (G - 1);
        int r0 = S * y - S / 2;
        float acc = 0.0f, wsum = 0.0f;
#pragma unroll
        for (int k = 0; k < NT; k++) {
            int r = r0 + k;
            if (r >= 0 && r < PS) {
                float w = (1.0f - fabsf((float)k - ((float)S - 0.5f)) / (float)S) / (float)S;
                acc  += w * tmp[(r - rb) * G + x];
                wsum += w;
            }
        }
        o[y * G + x] = acc / wsum;
    }
}

// Grid (1344 blocks), heavy work first:
//   [0, 768)     : S=4, 4 slices x 16 rows per (b,c)
//   [768, 1152)  : S=2, 2 slices x 32 rows per (b,c)
//   [1152, 1344) : direct 64x64 zero-padded crop of img0
__global__ __launch_bounds__(NTHREADS)
void glimpse_kernel(const float* __restrict__ img0,
                    const float* __restrict__ img2,
                    const float* __restrict__ img4,
                    const float* __restrict__ loc,
                    float* __restrict__ out) {
    extern __shared__ float tmp[];

    int blk = blockIdx.x;
    int sel, bc, slice;
    if (blk < 768)       { sel = 0; bc = blk >> 2;          slice = blk & 3; }
    else if (blk < 1152) { sel = 1; bc = (blk - 768) >> 1;  slice = (blk - 768) & 1; }
    else                 { sel = 2; bc = blk - 1152;        slice = 0; }
    int b = bc / 3;
    int c = bc - b * 3;

    // start index, matching jnp: trunc(0.5f * ((loc + 1.0f) * 511.0f))
    float lx = loc[2 * b + 0];
    float ly = loc[2 * b + 1];
    int sx = (int)(0.5f * ((lx + 1.0f) * 511.0f));
    int sy = (int)(0.5f * ((ly + 1.0f) * 511.0f));

    if (sel == 0) {
        // window 2: 256x256 crop of img4, downsample x4 (16 output rows/block)
        const float* img = img4 + (size_t)(b * 3 + c) * IMGSZ * IMGSZ;
        float* o = out + (size_t)((b * 3 + 2) * 3 + c) * G * G;
        downsample_slice<4, 16>(img, o, sy - 128, sx - 128, slice * 16, tmp);
    } else if (sel == 1) {
        // window 1: 128x128 crop of img2, downsample x2 (32 output rows/block)
        const float* img = img2 + (size_t)(b * 3 + c) * IMGSZ * IMGSZ;
        float* o = out + (size_t)((b * 3 + 1) * 3 + c) * G * G;
        downsample_slice<2, 32>(img, o, sy - 64, sx - 64, slice * 32, tmp);
    } else {
        // window 0: plain 64x64 zero-padded crop of img0
        const float* img = img0 + (size_t)(b * 3 + c) * IMGSZ * IMGSZ;
        float* o = out + (size_t)((b * 3 + 0) * 3 + c) * G * G;
        int by = sy - G / 2, bx = sx - G / 2;
        for (int idx = threadIdx.x; idx < G * G; idx += NTHREADS) {
            int y = idx >> 6, x = idx & (G - 1);
            o[idx] = ldimg(img, by + y, bx + x);
        }
    }
}

extern "C" void kernel_launch(void* const* d_in, const int* in_sizes, int n_in,
                              void* d_out, int out_size) {
    const float* img0 = (const float*)d_in[0];
    const float* img2 = (const float*)d_in[1];
    const float* img4 = (const float*)d_in[2];
    const float* loc  = (const float*)d_in[3];
    float* out = (float*)d_out;

    const size_t smem = (size_t)68 * G * sizeof(float);  // 68*64*4 = 17408 B
    cudaFuncSetAttribute(glimpse_kernel,
                         cudaFuncAttributeMaxDynamicSharedMemorySize, (int)smem);
    glimpse_kernel<<<1344, NTHREADS, smem>>>(img0, img2, img4, loc, out);
}